// round 2
// baseline (speedup 1.0000x reference)
#include <cuda_runtime.h>
#include <cuda_bf16.h>
#include <math.h>

// ---------------- problem constants ----------------
#define NS    16384      // batch
#define DIMX  3200       // feature dim
#define LMAX  4

// per-m segment sizes (K_m = Nout_m), prefix offsets in the 3200-wide layout
__constant__ int c_P[5]   = {0, 640, 1664, 2432, 2944};
__constant__ int c_K[5]   = {640, 1024, 768, 512, 256};
// J / DT per-l offsets (l=1..4), sizes 9,25,49,81, total 164
__constant__ int c_offD[4] = {0, 9, 34, 83};
// W_eff offsets for m=1..4 (sizes 1024^2, 768^2, 512^2, 256^2)
__constant__ size_t c_Woff[5] = {0, 0, 1048576, 1638400, 1900544};

// ---------------- device scratch (static allocation: allowed) ----------------
__device__ float g_J[164];                       // J matrices l=1..4 (fp32)
__device__ float g_DT[(size_t)NS * 164];         // per-sample D^T, all l
__device__ float g_Weff[1966080];                // effective W for m=1..4
__device__ float g_U[(size_t)NS * DIMX];         // gathered rotated inputs (per-m blocks)
__device__ float g_Z[(size_t)NS * DIMX];         // GEMM outputs (per-m blocks)

// =======================================================================
// Kernel 0: build J matrices (reference algorithm, fp64, one thread per l)
// =======================================================================
__device__ void mm9(const double* A, const double* B, double* C, int d) {
    for (int i = 0; i < d; i++)
        for (int j = 0; j < d; j++) {
            double s = 0.0;
            for (int k = 0; k < d; k++) s += A[i*9+k] * B[k*9+j];
            C[i*9+j] = s;
        }
}

__global__ void build_J_kernel() {
    int l = threadIdx.x + 1;
    if (l > LMAX) return;
    const int d = 2*l + 1;
    const double j = (double)l;
    const double SQ12 = 0.70710678118654752440;
    const double PI_D = 3.14159265358979323846;

    double Xr[81], Xi[81], Qr[81], Qi[81];
    for (int a = 0; a < 81; a++) { Xr[a]=0; Xi[a]=0; Qr[a]=0; Qi[a]=0; }

    // su2: X0 = 0.5*(raising + lowering)  (real), X1 = i*diag(m) (imag)
    for (int i2 = 0; i2 < d-1; i2++) {
        double m  = -j + (double)i2;
        double rv = -sqrt(j*(j+1.0) - m*(m+1.0));        // raising[i2+1, i2]
        Xr[(i2+1)*9 + i2] += 0.5 * rv;
        double m2 = -j + 1.0 + (double)i2;
        double lv = sqrt(j*(j+1.0) - m2*(m2-1.0));       // lowering[i2, i2+1]
        Xr[i2*9 + (i2+1)] += 0.5 * lv;
    }
    for (int i2 = 0; i2 < d; i2++) Xi[i2*9 + i2] += (-j + (double)i2);

    // Q (global phase (-i)^l cancels in Q^H X Q, omitted)
    for (int m = 1; m <= l; m++) {
        int r = l - m;                                   // row for -m
        Qr[r*9 + (l+m)] = SQ12;
        Qi[r*9 + r]     = -SQ12;
        int r2 = l + m;
        double sgn = (m & 1) ? -1.0 : 1.0;
        Qr[r2*9 + r2]     = sgn * SQ12;
        Qi[r2*9 + (l-m)]  = sgn * SQ12;
    }
    Qr[l*9 + l] = 1.0;

    // M = X @ Q (complex)
    double Mr[81], Mi[81];
    for (int i = 0; i < d; i++)
        for (int jj = 0; jj < d; jj++) {
            double sr = 0, si = 0;
            for (int k = 0; k < d; k++) {
                sr += Xr[i*9+k]*Qr[k*9+jj] - Xi[i*9+k]*Qi[k*9+jj];
                si += Xr[i*9+k]*Qi[k*9+jj] + Xi[i*9+k]*Qr[k*9+jj];
            }
            Mr[i*9+jj] = sr; Mi[i*9+jj] = si;
        }
    // A = (pi/sqrt2) * Re(Q^H M)
    double Amat[81];
    const double f = PI_D * SQ12;
    for (int i = 0; i < d; i++)
        for (int jj = 0; jj < d; jj++) {
            double s = 0;
            for (int k = 0; k < d; k++)
                s += Qr[k*9+i]*Mr[k*9+jj] + Qi[k*9+i]*Mi[k*9+jj];
            Amat[i*9+jj] = f * s;
        }

    // expm: scale 2^-10, Taylor order 24, square 10x  (matches reference)
    double As[81], E[81], T[81], Tm[81];
    for (int a = 0; a < 81; a++) { As[a] = Amat[a] * (1.0/1024.0); E[a]=0; T[a]=0; }
    for (int i = 0; i < d; i++) { E[i*9+i] = 1.0; T[i*9+i] = 1.0; }
    for (int k = 1; k < 24; k++) {
        mm9(T, As, Tm, d);
        double inv = 1.0 / (double)k;
        for (int i = 0; i < d; i++)
            for (int jj = 0; jj < d; jj++) {
                T[i*9+jj] = Tm[i*9+jj] * inv;
                E[i*9+jj] += T[i*9+jj];
            }
    }
    for (int s = 0; s < 10; s++) {
        mm9(E, E, Tm, d);
        for (int a = 0; a < 81; a++) E[a] = Tm[a];
    }

    float* dst = g_J + c_offD[l-1];
    for (int i = 0; i < d; i++)
        for (int jj = 0; jj < d; jj++)
            dst[i*d + jj] = (float)E[i*9 + jj];
}

// =======================================================================
// Kernel 1: build W_eff = [[A,-B],[B,A]] for m=1..4
// =======================================================================
__global__ void build_weff_kernel(const float* __restrict__ w1, const float* __restrict__ w2,
                                  const float* __restrict__ w3, const float* __restrict__ w4) {
    int gid = blockIdx.x * blockDim.x + threadIdx.x;
    if (gid >= 1966080) return;
    const float* w; int local, co;
    if (gid < 1048576)      { w = w1; local = gid;            co = 512; }
    else if (gid < 1638400) { w = w2; local = gid - 1048576;  co = 384; }
    else if (gid < 1900544) { w = w3; local = gid - 1638400;  co = 256; }
    else                    { w = w4; local = gid - 1900544;  co = 128; }
    int tco = 2 * co;
    int o = local / tco;
    int t = local - o * tco;
    float v;
    if (t < co)       v = w[o * co + t];
    else if (o < co)  v = -w[(o + co) * co + (t - co)];
    else              v =  w[(o - co) * co + (t - co)];
    g_Weff[gid] = v;
}

// =======================================================================
// Kernel 2: per-sample Wigner D^T matrices (thread per (n,l))
//   D = Z(alpha) @ J @ Z(beta) @ J
// =======================================================================
__global__ void wigner_kernel(const float* __restrict__ R) {
    int gid = blockIdx.x * blockDim.x + threadIdx.x;
    if (gid >= NS * 4) return;
    int n = gid >> 2;
    int l = (gid & 3) + 1;
    int d = 2*l + 1;

    float vx = R[n*3 + 1], vy = R[n*3 + 2], vz = R[n*3 + 0];
    float nrm = sqrtf(vx*vx + vy*vy + vz*vz);
    nrm = fmaxf(nrm, 1e-12f);
    vx /= nrm; vy /= nrm; vz /= nrm;
    vx = fminf(fmaxf(vx, -1.f), 1.f);
    vy = fminf(fmaxf(vy, -1.f), 1.f);
    vz = fminf(fmaxf(vz, -1.f), 1.f);
    float beta  = acosf(vy);
    float alpha = atan2f(vx, vz);

    const float* J = g_J + c_offD[l-1];
    float T1[81], T2[81], Dm[81];

    // T1 = Z(beta) @ J : row i = cos(f_i b)*J[i,:] + sin(f_i b)*J[d-1-i,:]
    for (int i = 0; i < d; i++) {
        float fr = (float)(l - i);
        float c = cosf(fr * beta), s = sinf(fr * beta);
        int ri = d - 1 - i;
        for (int jj = 0; jj < d; jj++)
            T1[i*d + jj] = c * J[i*d + jj] + s * J[ri*d + jj];
    }
    // T2 = J @ T1  =  J @ Z(beta) @ J     (left-multiply; fixed order)
    for (int i = 0; i < d; i++)
        for (int jj = 0; jj < d; jj++) {
            float s = 0.f;
            for (int k = 0; k < d; k++) s += J[i*d + k] * T1[k*d + jj];
            T2[i*d + jj] = s;
        }
    // D = Z(alpha) @ T2
    for (int i = 0; i < d; i++) {
        float fr = (float)(l - i);
        float c = cosf(fr * alpha), s = sinf(fr * alpha);
        int ri = d - 1 - i;
        for (int jj = 0; jj < d; jj++)
            Dm[i*d + jj] = c * T2[i*d + jj] + s * T2[ri*d + jj];
    }
    // store D^T
    float* dst = g_DT + (size_t)n * 164 + c_offD[l-1];
    for (int i = 0; i < d; i++)
        for (int jj = 0; jj < d; jj++)
            dst[i*d + jj] = Dm[jj*d + i];
}

// ---------------- index decode: linear e in [0,3200) -> (m,j,l,k,i) ----------------
__device__ __forceinline__ void decode_e(int e, int& m, int& j, int& l, int& k, int& i) {
    if (e < 640) {
        m = 0; j = e; l = e >> 7; k = e & 127; i = l;
    } else {
        if (e < 1664)      { m = 1; j = e - 640;  }
        else if (e < 2432) { m = 2; j = e - 1664; }
        else if (e < 2944) { m = 3; j = e - 2432; }
        else               { m = 4; j = e - 2944; }
        int bl = j >> 8, r = j & 255;
        k = r >> 1;
        l = m + bl;
        i = (r & 1) ? (l + m) : (l - m);
    }
}

// =======================================================================
// Kernel 3: rotate x -> x_rot, gather into per-m GEMM input buffers
// =======================================================================
__global__ void rot_gather_kernel(const float* __restrict__ x) {
    int n = blockIdx.x;
    __shared__ float xs[DIMX];
    __shared__ float dt[164];
    const float* xr = x + (size_t)n * DIMX;
    for (int c = threadIdx.x; c < DIMX; c += 256) xs[c] = xr[c];
    for (int c = threadIdx.x; c < 164; c += 256) dt[c] = g_DT[(size_t)n * 164 + c];
    __syncthreads();
    for (int e = threadIdx.x; e < DIMX; e += 256) {
        int m, j, l, k, i;
        decode_e(e, m, j, l, k, i);
        float val = 0.f;
        if (l > 0) {
            int d = 2*l + 1;
            const float* dd = dt + c_offD[l-1] + i*d;
            const float* xb = xs + 128*l*l + k*d;
            for (int jj = 0; jj < d; jj++) val += dd[jj] * xb[jj];
        }
        g_U[(size_t)NS * c_P[m] + (size_t)n * c_K[m] + j] = val;
    }
}

// =======================================================================
// Kernel 4: GEMM  C[r,o] = sum_t A[r,t] * W[o,t]  (128x128x16, dbl-buffered)
// =======================================================================
__device__ __forceinline__ void stage_tile(float (*S)[128], int lc, int lr, float4 v0, float4 v1) {
    S[lc+0][lr] = v0.x; S[lc+1][lr] = v0.y; S[lc+2][lr] = v0.z; S[lc+3][lr] = v0.w;
    S[lc+0][lr+64] = v1.x; S[lc+1][lr+64] = v1.y; S[lc+2][lr+64] = v1.z; S[lc+3][lr+64] = v1.w;
}

__global__ __launch_bounds__(256) void sgemm_kernel(const float* __restrict__ Bext, int m, int K) {
    const float* __restrict__ A = g_U + (size_t)NS * c_P[m];
    const float* __restrict__ B = (m == 0) ? Bext : (g_Weff + c_Woff[m]);
    float* __restrict__ C = g_Z + (size_t)NS * c_P[m];
    const int Nn = K;

    __shared__ float As[2][16][128];
    __shared__ float Bs[2][16][128];

    int tid = threadIdx.x;
    int brow = blockIdx.y << 7;
    int bcol = blockIdx.x << 7;
    int lr = tid >> 2;
    int lc = (tid & 3) << 2;
    const float* Ag = A + (size_t)(brow + lr) * K + lc;
    const float* Bg = B + (size_t)(bcol + lr) * K + lc;
    int ty = tid >> 4, tx = tid & 15;

    float acc[8][8];
    #pragma unroll
    for (int i = 0; i < 8; i++)
        #pragma unroll
        for (int jj = 0; jj < 8; jj++) acc[i][jj] = 0.f;

    float4 ra0 = *(const float4*)(Ag);
    float4 ra1 = *(const float4*)(Ag + (size_t)64 * K);
    float4 rb0 = *(const float4*)(Bg);
    float4 rb1 = *(const float4*)(Bg + (size_t)64 * K);
    stage_tile(As[0], lc, lr, ra0, ra1);
    stage_tile(Bs[0], lc, lr, rb0, rb1);
    __syncthreads();

    int KT = K >> 4;
    int buf = 0;
    for (int kt = 0; kt < KT; ++kt) {
        bool has = (kt + 1 < KT);
        if (has) {
            const float* Agn = Ag + ((kt + 1) << 4);
            const float* Bgn = Bg + ((kt + 1) << 4);
            ra0 = *(const float4*)(Agn);
            ra1 = *(const float4*)(Agn + (size_t)64 * K);
            rb0 = *(const float4*)(Bgn);
            rb1 = *(const float4*)(Bgn + (size_t)64 * K);
        }
        float (*Asb)[128] = As[buf];
        float (*Bsb)[128] = Bs[buf];
        #pragma unroll
        for (int kk = 0; kk < 16; kk++) {
            float a[8], b[8];
            *(float4*)(a)     = *(const float4*)&Asb[kk][ty << 2];
            *(float4*)(a + 4) = *(const float4*)&Asb[kk][(ty << 2) + 64];
            *(float4*)(b)     = *(const float4*)&Bsb[kk][tx << 2];
            *(float4*)(b + 4) = *(const float4*)&Bsb[kk][(tx << 2) + 64];
            #pragma unroll
            for (int i = 0; i < 8; i++)
                #pragma unroll
                for (int jj = 0; jj < 8; jj++)
                    acc[i][jj] = fmaf(a[i], b[jj], acc[i][jj]);
        }
        if (has) {
            int nb = buf ^ 1;
            stage_tile(As[nb], lc, lr, ra0, ra1);
            stage_tile(Bs[nb], lc, lr, rb0, rb1);
            __syncthreads();
            buf = nb;
        }
    }

    int r0 = brow + (ty << 2), r1 = r0 + 64;
    int c0 = bcol + (tx << 2), c1 = c0 + 64;
    #pragma unroll
    for (int i = 0; i < 4; i++) {
        *(float4*)&C[(size_t)(r0 + i) * Nn + c0] = make_float4(acc[i][0], acc[i][1], acc[i][2], acc[i][3]);
        *(float4*)&C[(size_t)(r0 + i) * Nn + c1] = make_float4(acc[i][4], acc[i][5], acc[i][6], acc[i][7]);
        *(float4*)&C[(size_t)(r1 + i) * Nn + c0] = make_float4(acc[i+4][0], acc[i+4][1], acc[i+4][2], acc[i+4][3]);
        *(float4*)&C[(size_t)(r1 + i) * Nn + c1] = make_float4(acc[i+4][4], acc[i+4][5], acc[i+4][6], acc[i+4][7]);
    }
}

// =======================================================================
// Kernel 5: scatter Z back to feature layout (+bias), rotate back, write out
// =======================================================================
__global__ void scatter_rot_kernel(const float* __restrict__ fc0_b, float* __restrict__ out) {
    int n = blockIdx.x;
    __shared__ float pre[DIMX];
    __shared__ float dt[164];
    for (int c = threadIdx.x; c < 164; c += 256) dt[c] = g_DT[(size_t)n * 164 + c];
    for (int e = threadIdx.x; e < DIMX; e += 256) {
        int m, j, l, k, i;
        decode_e(e, m, j, l, k, i);
        float v = g_Z[(size_t)NS * c_P[m] + (size_t)n * c_K[m] + j];
        if (m == 0) v += fc0_b[j];
        pre[128*l*l + k*(2*l + 1) + i] = v;
    }
    __syncthreads();
    for (int col = threadIdx.x; col < DIMX; col += 256) {
        int l;
        if (col < 128) l = 0;
        else if (col < 512) l = 1;
        else if (col < 1152) l = 2;
        else if (col < 2048) l = 3;
        else l = 4;
        float val;
        if (l == 0) {
            val = pre[col];
        } else {
            int off = 128*l*l;
            int d = 2*l + 1;
            int rr = col - off;
            int k = rr / d;
            int i = rr - k * d;
            const float* dd = dt + c_offD[l-1] + i*d;
            const float* pb = pre + off + k*d;
            float s = 0.f;
            for (int jj = 0; jj < d; jj++) s += dd[jj] * pb[jj];
            val = s;
        }
        out[(size_t)n * DIMX + col] = val;
    }
}

// =======================================================================
// launch
// =======================================================================
extern "C" void kernel_launch(void* const* d_in, const int* in_sizes, int n_in,
                              void* d_out, int out_size) {
    const float* x     = (const float*)d_in[0];
    const float* R     = (const float*)d_in[1];
    const float* fc0_w = (const float*)d_in[2];
    const float* fc0_b = (const float*)d_in[3];
    const float* w1    = (const float*)d_in[4];
    const float* w2    = (const float*)d_in[5];
    const float* w3    = (const float*)d_in[6];
    const float* w4    = (const float*)d_in[7];
    float* out = (float*)d_out;

    build_J_kernel<<<1, 4>>>();
    build_weff_kernel<<<(1966080 + 255) / 256, 256>>>(w1, w2, w3, w4);
    wigner_kernel<<<(NS * 4 + 127) / 128, 128>>>(R);
    rot_gather_kernel<<<NS, 256>>>(x);

    const int Ks[5] = {640, 1024, 768, 512, 256};
    for (int m = 0; m < 5; m++) {
        dim3 grid(Ks[m] / 128, NS / 128);
        sgemm_kernel<<<grid, 256>>>(m == 0 ? fc0_w : nullptr, m, Ks[m]);
    }

    scatter_rot_kernel<<<NS, 256>>>(fc0_b, out);
}

// round 4
// speedup vs baseline: 1.2346x; 1.2346x over previous
#include <cuda_runtime.h>
#include <cuda_bf16.h>
#include <math.h>
#include <stdint.h>

// ---------------- problem constants ----------------
#define NS    16384      // batch
#define DIMX  3200       // feature dim
#define LMAX  4

__constant__ int c_P[5]   = {0, 640, 1664, 2432, 2944};
__constant__ int c_K[5]   = {640, 1024, 768, 512, 256};
__constant__ int c_K3[5]  = {1920, 3072, 2304, 1536, 768};
__constant__ int c_P3[5]  = {0, 1920, 4992, 7296, 8832};
__constant__ int c_offD[4] = {0, 9, 34, 83};

// ---------------- device scratch ----------------
__device__ float g_J[164];
__device__ float g_DT[(size_t)NS * 164];
__device__ __nv_bfloat16 g_W3[7127040];               // [N, 3K] bf16 weights (hi|hi|lo)
__device__ __nv_bfloat16 g_U3[(size_t)NS * 9600];     // [NS, 3K] bf16 inputs (hi|lo|hi)
__device__ float g_Z[(size_t)NS * DIMX];              // GEMM outputs

// =======================================================================
// Kernel 0: build J matrices (reference algorithm, fp64)
// =======================================================================
__device__ void mm9(const double* A, const double* B, double* C, int d) {
    for (int i = 0; i < d; i++)
        for (int j = 0; j < d; j++) {
            double s = 0.0;
            for (int k = 0; k < d; k++) s += A[i*9+k] * B[k*9+j];
            C[i*9+j] = s;
        }
}

__global__ void build_J_kernel() {
    int l = threadIdx.x + 1;
    if (l > LMAX) return;
    const int d = 2*l + 1;
    const double j = (double)l;
    const double SQ12 = 0.70710678118654752440;
    const double PI_D = 3.14159265358979323846;

    double Xr[81], Xi[81], Qr[81], Qi[81];
    for (int a = 0; a < 81; a++) { Xr[a]=0; Xi[a]=0; Qr[a]=0; Qi[a]=0; }

    for (int i2 = 0; i2 < d-1; i2++) {
        double m  = -j + (double)i2;
        double rv = -sqrt(j*(j+1.0) - m*(m+1.0));
        Xr[(i2+1)*9 + i2] += 0.5 * rv;
        double m2 = -j + 1.0 + (double)i2;
        double lv = sqrt(j*(j+1.0) - m2*(m2-1.0));
        Xr[i2*9 + (i2+1)] += 0.5 * lv;
    }
    for (int i2 = 0; i2 < d; i2++) Xi[i2*9 + i2] += (-j + (double)i2);

    for (int m = 1; m <= l; m++) {
        int r = l - m;
        Qr[r*9 + (l+m)] = SQ12;
        Qi[r*9 + r]     = -SQ12;
        int r2 = l + m;
        double sgn = (m & 1) ? -1.0 : 1.0;
        Qr[r2*9 + r2]     = sgn * SQ12;
        Qi[r2*9 + (l-m)]  = sgn * SQ12;
    }
    Qr[l*9 + l] = 1.0;

    double Mr[81], Mi[81];
    for (int i = 0; i < d; i++)
        for (int jj = 0; jj < d; jj++) {
            double sr = 0, si = 0;
            for (int k = 0; k < d; k++) {
                sr += Xr[i*9+k]*Qr[k*9+jj] - Xi[i*9+k]*Qi[k*9+jj];
                si += Xr[i*9+k]*Qi[k*9+jj] + Xi[i*9+k]*Qr[k*9+jj];
            }
            Mr[i*9+jj] = sr; Mi[i*9+jj] = si;
        }
    double Amat[81];
    const double f = PI_D * SQ12;
    for (int i = 0; i < d; i++)
        for (int jj = 0; jj < d; jj++) {
            double s = 0;
            for (int k = 0; k < d; k++)
                s += Qr[k*9+i]*Mr[k*9+jj] + Qi[k*9+i]*Mi[k*9+jj];
            Amat[i*9+jj] = f * s;
        }

    double As[81], E[81], T[81], Tm[81];
    for (int a = 0; a < 81; a++) { As[a] = Amat[a] * (1.0/1024.0); E[a]=0; T[a]=0; }
    for (int i = 0; i < d; i++) { E[i*9+i] = 1.0; T[i*9+i] = 1.0; }
    for (int k = 1; k < 24; k++) {
        mm9(T, As, Tm, d);
        double inv = 1.0 / (double)k;
        for (int i = 0; i < d; i++)
            for (int jj = 0; jj < d; jj++) {
                T[i*9+jj] = Tm[i*9+jj] * inv;
                E[i*9+jj] += T[i*9+jj];
            }
    }
    for (int s = 0; s < 10; s++) {
        mm9(E, E, Tm, d);
        for (int a = 0; a < 81; a++) E[a] = Tm[a];
    }

    float* dst = g_J + c_offD[l-1];
    for (int i = 0; i < d; i++)
        for (int jj = 0; jj < d; jj++)
            dst[i*d + jj] = (float)E[i*9 + jj];
}

// =======================================================================
// Kernel 1: build W3 = bf16 [N, 3K] (hi | hi | lo) for all m
// =======================================================================
__global__ void build_w3_kernel(const float* __restrict__ fc0_w,
                                const float* __restrict__ w1, const float* __restrict__ w2,
                                const float* __restrict__ w3, const float* __restrict__ w4) {
    int gid = blockIdx.x * blockDim.x + threadIdx.x;
    if (gid >= 7127040) return;
    int m; int local;
    if (gid < 1228800)      { m = 0; local = gid; }
    else if (gid < 4374528) { m = 1; local = gid - 1228800; }
    else if (gid < 6144000) { m = 2; local = gid - 4374528; }
    else if (gid < 6930432) { m = 3; local = gid - 6144000; }
    else                    { m = 4; local = gid - 6930432; }
    int K = c_K[m], K3 = 3 * K;
    int o = local / K3;
    int rem = local - o * K3;
    int seg = rem / K;
    int t = rem - seg * K;
    float v;
    if (m == 0) {
        v = fc0_w[o * 640 + t];
    } else {
        const float* w = (m == 1) ? w1 : (m == 2) ? w2 : (m == 3) ? w3 : w4;
        int co = K >> 1;
        if (t < co)       v = w[o * co + t];
        else if (o < co)  v = -w[(o + co) * co + (t - co)];
        else              v =  w[(o - co) * co + (t - co)];
    }
    __nv_bfloat16 hi = __float2bfloat16(v);
    __nv_bfloat16 outv;
    if (seg == 2) outv = __float2bfloat16(v - __bfloat162float(hi));  // lo in last third
    else          outv = hi;                                          // hi | hi | lo
    g_W3[gid] = outv;
}

// =======================================================================
// Kernel 2: per-sample Wigner D^T (D = Z(a) J Z(b) J)
// =======================================================================
__global__ void wigner_kernel(const float* __restrict__ R) {
    int gid = blockIdx.x * blockDim.x + threadIdx.x;
    if (gid >= NS * 4) return;
    int n = gid >> 2;
    int l = (gid & 3) + 1;
    int d = 2*l + 1;

    float vx = R[n*3 + 1], vy = R[n*3 + 2], vz = R[n*3 + 0];
    float nrm = sqrtf(vx*vx + vy*vy + vz*vz);
    nrm = fmaxf(nrm, 1e-12f);
    vx /= nrm; vy /= nrm; vz /= nrm;
    vx = fminf(fmaxf(vx, -1.f), 1.f);
    vy = fminf(fmaxf(vy, -1.f), 1.f);
    vz = fminf(fmaxf(vz, -1.f), 1.f);
    float beta  = acosf(vy);
    float alpha = atan2f(vx, vz);

    const float* J = g_J + c_offD[l-1];
    float T1[81], T2[81], Dm[81];

    for (int i = 0; i < d; i++) {
        float fr = (float)(l - i);
        float c = cosf(fr * beta), s = sinf(fr * beta);
        int ri = d - 1 - i;
        for (int jj = 0; jj < d; jj++)
            T1[i*d + jj] = c * J[i*d + jj] + s * J[ri*d + jj];
    }
    for (int i = 0; i < d; i++)
        for (int jj = 0; jj < d; jj++) {
            float s = 0.f;
            for (int k = 0; k < d; k++) s += J[i*d + k] * T1[k*d + jj];
            T2[i*d + jj] = s;
        }
    for (int i = 0; i < d; i++) {
        float fr = (float)(l - i);
        float c = cosf(fr * alpha), s = sinf(fr * alpha);
        int ri = d - 1 - i;
        for (int jj = 0; jj < d; jj++)
            Dm[i*d + jj] = c * T2[i*d + jj] + s * T2[ri*d + jj];
    }
    float* dst = g_DT + (size_t)n * 164 + c_offD[l-1];
    for (int i = 0; i < d; i++)
        for (int jj = 0; jj < d; jj++)
            dst[i*d + jj] = Dm[jj*d + i];
}

// ---------------- index decode ----------------
__device__ __forceinline__ void decode_e(int e, int& m, int& j, int& l, int& k, int& i) {
    if (e < 640) {
        m = 0; j = e; l = e >> 7; k = e & 127; i = l;
    } else {
        if (e < 1664)      { m = 1; j = e - 640;  }
        else if (e < 2432) { m = 2; j = e - 1664; }
        else if (e < 2944) { m = 3; j = e - 2432; }
        else               { m = 4; j = e - 2944; }
        int bl = j >> 8, r = j & 255;
        k = r >> 1;
        l = m + bl;
        i = (r & 1) ? (l + m) : (l - m);
    }
}

// =======================================================================
// Kernel 3: rotate x, gather into bf16 hi|lo|hi GEMM input rows
// =======================================================================
__global__ void rot_gather_kernel(const float* __restrict__ x) {
    int n = blockIdx.x;
    __shared__ float xs[DIMX];
    __shared__ float dt[164];
    const float* xr = x + (size_t)n * DIMX;
    for (int c = threadIdx.x; c < DIMX; c += 256) xs[c] = xr[c];
    for (int c = threadIdx.x; c < 164; c += 256) dt[c] = g_DT[(size_t)n * 164 + c];
    __syncthreads();
    for (int e = threadIdx.x; e < DIMX; e += 256) {
        int m, j, l, k, i;
        decode_e(e, m, j, l, k, i);
        float val = 0.f;
        if (l > 0) {
            int d = 2*l + 1;
            const float* dd = dt + c_offD[l-1] + i*d;
            const float* xb = xs + 128*l*l + k*d;
            for (int jj = 0; jj < d; jj++) val += dd[jj] * xb[jj];
        }
        int K = c_K[m];
        __nv_bfloat16 hi = __float2bfloat16(val);
        __nv_bfloat16 lo = __float2bfloat16(val - __bfloat162float(hi));
        size_t base = (size_t)NS * c_P3[m] + (size_t)n * (3 * K);
        g_U3[base + j]         = hi;   // hi | lo | hi
        g_U3[base + K + j]     = lo;
        g_U3[base + 2 * K + j] = hi;
    }
}

// =======================================================================
// Kernel 4: HMMA bf16 GEMM  C[r,o] = sum_t A3[r,t]*W3[o,t]  (K' = 3K)
//   CTA 128x128, 8 warps (32x64 each), K-chunk 64, cp.async 2-stage,
//   SW128-swizzled SMEM, ldmatrix.x4, mma.sync m16n8k16 bf16
// =======================================================================
__device__ __forceinline__ uint32_t smem_u32(const void* p) {
    uint32_t a;
    asm("{ .reg .u64 t; cvta.to.shared.u64 t, %1; cvt.u32.u64 %0, t; }" : "=r"(a) : "l"(p));
    return a;
}
#define CP_ASYNC16(dst, src) \
    asm volatile("cp.async.cg.shared.global [%0], [%1], 16;" :: "r"(dst), "l"(src) : "memory")
#define CP_COMMIT() asm volatile("cp.async.commit_group;" ::: "memory")
#define CP_WAIT1()  asm volatile("cp.async.wait_group 1;" ::: "memory")
#define CP_WAIT0()  asm volatile("cp.async.wait_group 0;" ::: "memory")
#define LDSM_X4(r0, r1, r2, r3, addr) \
    asm volatile("ldmatrix.sync.aligned.m8n8.x4.shared.b16 {%0,%1,%2,%3}, [%4];" \
                 : "=r"(r0), "=r"(r1), "=r"(r2), "=r"(r3) : "r"(addr))

__device__ __forceinline__ void hmma16816(float* c, const uint32_t* a, const uint32_t* b) {
    asm volatile(
        "mma.sync.aligned.m16n8k16.row.col.f32.bf16.bf16.f32 "
        "{%0,%1,%2,%3}, {%4,%5,%6,%7}, {%8,%9}, {%0,%1,%2,%3};"
        : "+f"(c[0]), "+f"(c[1]), "+f"(c[2]), "+f"(c[3])
        : "r"(a[0]), "r"(a[1]), "r"(a[2]), "r"(a[3]), "r"(b[0]), "r"(b[1]));
}

__global__ __launch_bounds__(256) void hmma_gemm_kernel(
        const __nv_bfloat16* __restrict__ A, const __nv_bfloat16* __restrict__ B,
        float* __restrict__ C, int K3, int N) {
    extern __shared__ __align__(1024) char dsm[];
    uint32_t sbase = smem_u32(dsm);

    int tid = threadIdx.x;
    int wid = tid >> 5;
    int lane = tid & 31;
    int brow = blockIdx.y << 7;
    int bcol = blockIdx.x << 7;

    // ---- global->smem mapping: 2 threads/row, 4x16B each ----
    int r = tid >> 1, q = tid & 1;
    const char* gA = (const char*)(A + (size_t)(brow + r) * K3 + q * 32);
    const char* gB = (const char*)(B + (size_t)(bcol + r) * K3 + q * 32);
    uint32_t sts[4];
    #pragma unroll
    for (int i = 0; i < 4; i++) {
        uint32_t off = (uint32_t)r * 128u + (uint32_t)(q * 4 + i) * 16u;
        sts[i] = off ^ ((off >> 3) & 0x70);
    }

    // ---- per-warp compute layout ----
    int wm = wid >> 1, wn = wid & 1;
    uint32_t a_row[2], a_rx[2];
    #pragma unroll
    for (int mt = 0; mt < 2; mt++) {
        int row = wm * 32 + mt * 16 + (lane & 15);
        a_row[mt] = (uint32_t)row * 128u;
        a_rx[mt] = (uint32_t)(row & 7) << 4;
    }
    uint32_t a_cb = ((lane >> 4) & 1) * 16u;
    int nloc = (lane & 7) + ((lane & 16) >> 1);
    uint32_t b_row[4], b_rx[4];
    #pragma unroll
    for (int nt4 = 0; nt4 < 4; nt4++) {
        int nrow = wn * 64 + nt4 * 16 + nloc;
        b_row[nt4] = (uint32_t)nrow * 128u;
        b_rx[nt4] = (uint32_t)(nrow & 7) << 4;
    }
    uint32_t b_cb = ((lane >> 3) & 1) * 16u;

    float acc[2][8][4];
    #pragma unroll
    for (int mt = 0; mt < 2; mt++)
        #pragma unroll
        for (int nt = 0; nt < 8; nt++)
            #pragma unroll
            for (int e = 0; e < 4; e++) acc[mt][nt][e] = 0.f;

    int NC = K3 >> 6;

    // prologue: load chunk 0 into buf 0
    {
        uint32_t aS = sbase, bS = sbase + 32768u;
        #pragma unroll
        for (int i = 0; i < 4; i++) {
            CP_ASYNC16(aS + sts[i], gA + i * 16);
            CP_ASYNC16(bS + sts[i], gB + i * 16);
        }
        CP_COMMIT();
    }

    for (int c = 0; c < NC; ++c) {
        int buf = c & 1;
        if (c + 1 < NC) {
            int nb = buf ^ 1;
            uint32_t aS = sbase + (uint32_t)nb * 16384u;
            uint32_t bS = sbase + 32768u + (uint32_t)nb * 16384u;
            const char* Ap = gA + (size_t)(c + 1) * 128;
            const char* Bp = gB + (size_t)(c + 1) * 128;
            #pragma unroll
            for (int i = 0; i < 4; i++) {
                CP_ASYNC16(aS + sts[i], Ap + i * 16);
                CP_ASYNC16(bS + sts[i], Bp + i * 16);
            }
            CP_COMMIT();
            CP_WAIT1();
        } else {
            CP_WAIT0();
        }
        __syncthreads();

        uint32_t aS = sbase + (uint32_t)buf * 16384u;
        uint32_t bS = sbase + 32768u + (uint32_t)buf * 16384u;
        #pragma unroll
        for (int kq = 0; kq < 4; kq++) {
            uint32_t kb = (uint32_t)kq * 32u;
            uint32_t afr[2][4];
            #pragma unroll
            for (int mt = 0; mt < 2; mt++)
                LDSM_X4(afr[mt][0], afr[mt][1], afr[mt][2], afr[mt][3],
                        aS + a_row[mt] + ((a_cb + kb) ^ a_rx[mt]));
            uint32_t bfr[4][4];
            #pragma unroll
            for (int nt4 = 0; nt4 < 4; nt4++)
                LDSM_X4(bfr[nt4][0], bfr[nt4][1], bfr[nt4][2], bfr[nt4][3],
                        bS + b_row[nt4] + ((b_cb + kb) ^ b_rx[nt4]));
            #pragma unroll
            for (int mt = 0; mt < 2; mt++)
                #pragma unroll
                for (int nt = 0; nt < 8; nt++)
                    hmma16816(acc[mt][nt], afr[mt], &bfr[nt >> 1][(nt & 1) * 2]);
        }
        __syncthreads();
    }

    // epilogue
    int g = lane >> 2, t = lane & 3;
    #pragma unroll
    for (int mt = 0; mt < 2; mt++) {
        #pragma unroll
        for (int nt = 0; nt < 8; nt++) {
            int row0 = brow + wm * 32 + mt * 16 + g;
            int col = bcol + wn * 64 + nt * 8 + t * 2;
            float2 v0 = make_float2(acc[mt][nt][0], acc[mt][nt][1]);
            float2 v1 = make_float2(acc[mt][nt][2], acc[mt][nt][3]);
            *(float2*)(C + (size_t)row0 * N + col) = v0;
            *(float2*)(C + (size_t)(row0 + 8) * N + col) = v1;
        }
    }
}

// =======================================================================
// Kernel 5: scatter Z back (+bias), rotate back, write out
// =======================================================================
__global__ void scatter_rot_kernel(const float* __restrict__ fc0_b, float* __restrict__ out) {
    int n = blockIdx.x;
    __shared__ float pre[DIMX];
    __shared__ float dt[164];
    for (int c = threadIdx.x; c < 164; c += 256) dt[c] = g_DT[(size_t)n * 164 + c];
    for (int e = threadIdx.x; e < DIMX; e += 256) {
        int m, j, l, k, i;
        decode_e(e, m, j, l, k, i);
        float v = g_Z[(size_t)NS * c_P[m] + (size_t)n * c_K[m] + j];
        if (m == 0) v += fc0_b[j];
        pre[128*l*l + k*(2*l + 1) + i] = v;
    }
    __syncthreads();
    for (int col = threadIdx.x; col < DIMX; col += 256) {
        int l;
        if (col < 128) l = 0;
        else if (col < 512) l = 1;
        else if (col < 1152) l = 2;
        else if (col < 2048) l = 3;
        else l = 4;
        float val;
        if (l == 0) {
            val = pre[col];
        } else {
            int off = 128*l*l;
            int d = 2*l + 1;
            int rr = col - off;
            int k = rr / d;
            int i = rr - k * d;
            const float* dd = dt + c_offD[l-1] + i*d;
            const float* pb = pre + off + k*d;
            float s = 0.f;
            for (int jj = 0; jj < d; jj++) s += dd[jj] * pb[jj];
            val = s;
        }
        out[(size_t)n * DIMX + col] = val;
    }
}

// =======================================================================
// launch
// =======================================================================
extern "C" void kernel_launch(void* const* d_in, const int* in_sizes, int n_in,
                              void* d_out, int out_size) {
    const float* x     = (const float*)d_in[0];
    const float* R     = (const float*)d_in[1];
    const float* fc0_w = (const float*)d_in[2];
    const float* fc0_b = (const float*)d_in[3];
    const float* w1    = (const float*)d_in[4];
    const float* w2    = (const float*)d_in[5];
    const float* w3    = (const float*)d_in[6];
    const float* w4    = (const float*)d_in[7];
    float* out = (float*)d_out;

    build_J_kernel<<<1, 4>>>();
    build_w3_kernel<<<(7127040 + 255) / 256, 256>>>(fc0_w, w1, w2, w3, w4);
    wigner_kernel<<<(NS * 4 + 127) / 128, 128>>>(R);
    rot_gather_kernel<<<NS, 256>>>(x);

    void *pU3 = nullptr, *pW3 = nullptr, *pZ = nullptr;
    cudaGetSymbolAddress(&pU3, g_U3);
    cudaGetSymbolAddress(&pW3, g_W3);
    cudaGetSymbolAddress(&pZ, g_Z);
    cudaFuncSetAttribute(hmma_gemm_kernel, cudaFuncAttributeMaxDynamicSharedMemorySize, 65536);

    const int Ks[5]   = {640, 1024, 768, 512, 256};
    const int K3s[5]  = {1920, 3072, 2304, 1536, 768};
    const int P3s[5]  = {0, 1920, 4992, 7296, 8832};
    const int Ps[5]   = {0, 640, 1664, 2432, 2944};
    const size_t W3off[5] = {0, 1228800, 4374528, 6144000, 6930432};

    for (int m = 0; m < 5; m++) {
        const __nv_bfloat16* A = (const __nv_bfloat16*)pU3 + (size_t)NS * P3s[m];
        const __nv_bfloat16* B = (const __nv_bfloat16*)pW3 + W3off[m];
        float* C = (float*)pZ + (size_t)NS * Ps[m];
        dim3 grid(Ks[m] / 128, NS / 128);
        hmma_gemm_kernel<<<grid, 256, 65536>>>(A, B, C, K3s[m], Ks[m]);
    }

    scatter_rot_kernel<<<NS, 256>>>(fc0_b, out);
}

// round 5
// speedup vs baseline: 4.9080x; 3.9754x over previous
#include <cuda_runtime.h>
#include <cuda_fp16.h>
#include <math.h>
#include <stdint.h>

// ---------------- problem constants ----------------
#define NS    16384      // batch
#define DIMX  3200       // feature dim
#define LMAX  4

__constant__ int c_P[5]   = {0, 640, 1664, 2432, 2944};
__constant__ int c_K[5]   = {640, 1024, 768, 512, 256};
__constant__ int c_offD[4] = {0, 9, 34, 83};
// W offsets per m (sizes 640^2, 1024^2, 768^2, 512^2, 256^2)
__constant__ size_t c_Woff[5] = {0, 409600, 1458176, 2048000, 2310144};

// ---------------- device scratch ----------------
__device__ float g_J[164];
__device__ float g_DT[(size_t)NS * 164];
__device__ __half g_W[2375680];                  // [N, K] fp16 weights, all m
__device__ __half g_U[(size_t)NS * DIMX];        // [NS, K] fp16 inputs, per-m blocks
__device__ float g_Z[(size_t)NS * DIMX];         // GEMM outputs

// =======================================================================
// Kernel 0: build J matrices (reference algorithm, fp64, parallel)
//   384 threads: group g = l-1 (96 threads each), element e < d*d
// =======================================================================
__global__ void build_J_kernel() {
    __shared__ double Xr[4][81], Xi[4][81], Qr[4][81], Qi[4][81];
    __shared__ double Sa[4][81], Se[4][81], St[4][81], Sm[4][81];
    int g = threadIdx.x / 96;
    int e = threadIdx.x % 96;
    int l = g + 1, d = 2*l + 1, dd = d*d;
    const double j = (double)l;
    const double SQ12 = 0.70710678118654752440;
    const double PI_D = 3.14159265358979323846;

    if (e < 81) { Xr[g][e]=0; Xi[g][e]=0; Qr[g][e]=0; Qi[g][e]=0; }
    __syncthreads();
    if (e == 0) {
        // su2 -> so3 generators: X0 real tridiag, X1 = i*diag(m); d-stride
        for (int i2 = 0; i2 < d-1; i2++) {
            double m  = -j + (double)i2;
            double rv = -sqrt(j*(j+1.0) - m*(m+1.0));
            Xr[g][(i2+1)*d + i2] += 0.5 * rv;
            double m2 = -j + 1.0 + (double)i2;
            double lv = sqrt(j*(j+1.0) - m2*(m2-1.0));
            Xr[g][i2*d + (i2+1)] += 0.5 * lv;
        }
        for (int i2 = 0; i2 < d; i2++) Xi[g][i2*d + i2] += (-j + (double)i2);
        for (int m = 1; m <= l; m++) {
            int r = l - m;
            Qr[g][r*d + (l+m)] = SQ12;
            Qi[g][r*d + r]     = -SQ12;
            int r2 = l + m;
            double sgn = (m & 1) ? -1.0 : 1.0;
            Qr[g][r2*d + r2]     = sgn * SQ12;
            Qi[g][r2*d + (l-m)]  = sgn * SQ12;
        }
        Qr[g][l*d + l] = 1.0;
    }
    __syncthreads();
    // Amat[i][jj] = f * Re( sum_k conj(Q)[k,i] * (X@Q)[k,jj] ), scaled 2^-10
    if (e < dd) {
        int i = e / d, jj = e % d;
        double s = 0.0;
        for (int k = 0; k < d; k++) {
            double mr = 0.0, mi = 0.0;
            for (int p = 0; p < d; p++) {
                mr += Xr[g][k*d+p]*Qr[g][p*d+jj] - Xi[g][k*d+p]*Qi[g][p*d+jj];
                mi += Xr[g][k*d+p]*Qi[g][p*d+jj] + Xi[g][k*d+p]*Qr[g][p*d+jj];
            }
            s += Qr[g][k*d+i]*mr + Qi[g][k*d+i]*mi;
        }
        Sa[g][e] = (PI_D * SQ12) * s * (1.0/1024.0);
        Se[g][e] = (i == jj) ? 1.0 : 0.0;
        St[g][e] = (i == jj) ? 1.0 : 0.0;
    }
    __syncthreads();
    // Taylor order 24
    for (int k = 1; k < 24; k++) {
        double v = 0.0;
        if (e < dd) {
            int i = e / d, jj = e % d;
            double s = 0.0;
            for (int p = 0; p < d; p++) s += St[g][i*d+p] * Sa[g][p*d+jj];
            v = s / (double)k;
        }
        __syncthreads();
        if (e < dd) { St[g][e] = v; Se[g][e] += v; }
        __syncthreads();
    }
    // 10 squarings
    for (int s2 = 0; s2 < 10; s2++) {
        double v = 0.0;
        if (e < dd) {
            int i = e / d, jj = e % d;
            double s = 0.0;
            for (int p = 0; p < d; p++) s += Se[g][i*d+p] * Se[g][p*d+jj];
            v = s;
        }
        __syncthreads();
        if (e < dd) Se[g][e] = v;
        __syncthreads();
    }
    if (e < dd) g_J[c_offD[g] + e] = (float)Se[g][e];
}

// =======================================================================
// Kernel 1: build W = fp16 [N, K] for all m (m=0 uses fc0_w; m>0 W_eff)
// =======================================================================
__global__ void build_w_kernel(const float* __restrict__ fc0_w,
                               const float* __restrict__ w1, const float* __restrict__ w2,
                               const float* __restrict__ w3, const float* __restrict__ w4) {
    int gid = blockIdx.x * blockDim.x + threadIdx.x;
    if (gid >= 2375680) return;
    int m; int local;
    if (gid < 409600)       { m = 0; local = gid; }
    else if (gid < 1458176) { m = 1; local = gid - 409600; }
    else if (gid < 2048000) { m = 2; local = gid - 1458176; }
    else if (gid < 2310144) { m = 3; local = gid - 2048000; }
    else                    { m = 4; local = gid - 2310144; }
    int K = c_K[m];
    int o = local / K;
    int t = local - o * K;
    float v;
    if (m == 0) {
        v = fc0_w[o * 640 + t];
    } else {
        const float* w = (m == 1) ? w1 : (m == 2) ? w2 : (m == 3) ? w3 : w4;
        int co = K >> 1;
        if (t < co)       v = w[o * co + t];
        else if (o < co)  v = -w[(o + co) * co + (t - co)];
        else              v =  w[(o - co) * co + (t - co)];
    }
    g_W[gid] = __float2half_rn(v);
}

// =======================================================================
// Kernel 2: per-sample Wigner D^T (D = Z(a) J Z(b) J)
// =======================================================================
__global__ void wigner_kernel(const float* __restrict__ R) {
    int gid = blockIdx.x * blockDim.x + threadIdx.x;
    if (gid >= NS * 4) return;
    int n = gid >> 2;
    int l = (gid & 3) + 1;
    int d = 2*l + 1;

    float vx = R[n*3 + 1], vy = R[n*3 + 2], vz = R[n*3 + 0];
    float nrm = sqrtf(vx*vx + vy*vy + vz*vz);
    nrm = fmaxf(nrm, 1e-12f);
    vx /= nrm; vy /= nrm; vz /= nrm;
    vx = fminf(fmaxf(vx, -1.f), 1.f);
    vy = fminf(fmaxf(vy, -1.f), 1.f);
    vz = fminf(fmaxf(vz, -1.f), 1.f);
    float beta  = acosf(vy);
    float alpha = atan2f(vx, vz);

    const float* J = g_J + c_offD[l-1];
    float T1[81], T2[81], Dm[81];

    for (int i = 0; i < d; i++) {
        float fr = (float)(l - i);
        float c = cosf(fr * beta), s = sinf(fr * beta);
        int ri = d - 1 - i;
        for (int jj = 0; jj < d; jj++)
            T1[i*d + jj] = c * J[i*d + jj] + s * J[ri*d + jj];
    }
    for (int i = 0; i < d; i++)
        for (int jj = 0; jj < d; jj++) {
            float s = 0.f;
            for (int k = 0; k < d; k++) s += J[i*d + k] * T1[k*d + jj];
            T2[i*d + jj] = s;
        }
    for (int i = 0; i < d; i++) {
        float fr = (float)(l - i);
        float c = cosf(fr * alpha), s = sinf(fr * alpha);
        int ri = d - 1 - i;
        for (int jj = 0; jj < d; jj++)
            Dm[i*d + jj] = c * T2[i*d + jj] + s * T2[ri*d + jj];
    }
    float* dst = g_DT + (size_t)n * 164 + c_offD[l-1];
    for (int i = 0; i < d; i++)
        for (int jj = 0; jj < d; jj++)
            dst[i*d + jj] = Dm[jj*d + i];
}

// ---------------- index decode ----------------
__device__ __forceinline__ void decode_e(int e, int& m, int& j, int& l, int& k, int& i) {
    if (e < 640) {
        m = 0; j = e; l = e >> 7; k = e & 127; i = l;
    } else {
        if (e < 1664)      { m = 1; j = e - 640;  }
        else if (e < 2432) { m = 2; j = e - 1664; }
        else if (e < 2944) { m = 3; j = e - 2432; }
        else               { m = 4; j = e - 2944; }
        int bl = j >> 8, r = j & 255;
        k = r >> 1;
        l = m + bl;
        i = (r & 1) ? (l + m) : (l - m);
    }
}

// =======================================================================
// Kernel 3: rotate x, gather into fp16 GEMM input rows
// =======================================================================
__global__ void rot_gather_kernel(const float* __restrict__ x) {
    int n = blockIdx.x;
    __shared__ float xs[DIMX];
    __shared__ float dt[164];
    const float* xr = x + (size_t)n * DIMX;
    for (int c = threadIdx.x; c < DIMX; c += 256) xs[c] = xr[c];
    for (int c = threadIdx.x; c < 164; c += 256) dt[c] = g_DT[(size_t)n * 164 + c];
    __syncthreads();
    for (int e = threadIdx.x; e < DIMX; e += 256) {
        int m, j, l, k, i;
        decode_e(e, m, j, l, k, i);
        float val = 0.f;
        if (l > 0) {
            int d = 2*l + 1;
            const float* dd = dt + c_offD[l-1] + i*d;
            const float* xb = xs + 128*l*l + k*d;
            for (int jj = 0; jj < d; jj++) val += dd[jj] * xb[jj];
        }
        g_U[(size_t)NS * c_P[m] + (size_t)n * c_K[m] + j] = __float2half_rn(val);
    }
}

// =======================================================================
// Kernel 4: HMMA fp16 GEMM, all m merged.  C[r,o] = sum_t A[r,t]*W[o,t]
//   CTA 128x128, 8 warps (32x64), K-chunk 64, cp.async 3-stage,
//   SW128-swizzled SMEM, ldmatrix.x4, mma.sync m16n8k16 f16 (f32 acc)
// =======================================================================
__device__ __forceinline__ uint32_t smem_u32(const void* p) {
    uint32_t a;
    asm("{ .reg .u64 t; cvta.to.shared.u64 t, %1; cvt.u32.u64 %0, t; }" : "=r"(a) : "l"(p));
    return a;
}
#define CP_ASYNC16(dst, src) \
    asm volatile("cp.async.cg.shared.global [%0], [%1], 16;" :: "r"(dst), "l"(src) : "memory")
#define CP_COMMIT() asm volatile("cp.async.commit_group;" ::: "memory")
#define CP_WAIT1()  asm volatile("cp.async.wait_group 1;" ::: "memory")
#define CP_WAIT0()  asm volatile("cp.async.wait_group 0;" ::: "memory")
#define LDSM_X4(r0, r1, r2, r3, addr) \
    asm volatile("ldmatrix.sync.aligned.m8n8.x4.shared.b16 {%0,%1,%2,%3}, [%4];" \
                 : "=r"(r0), "=r"(r1), "=r"(r2), "=r"(r3) : "r"(addr))

__device__ __forceinline__ void hmma16816(float* c, const uint32_t* a, const uint32_t* b) {
    asm volatile(
        "mma.sync.aligned.m16n8k16.row.col.f32.f16.f16.f32 "
        "{%0,%1,%2,%3}, {%4,%5,%6,%7}, {%8,%9}, {%0,%1,%2,%3};"
        : "+f"(c[0]), "+f"(c[1]), "+f"(c[2]), "+f"(c[3])
        : "r"(a[0]), "r"(a[1]), "r"(a[2]), "r"(a[3]), "r"(b[0]), "r"(b[1]));
}

__global__ __launch_bounds__(256) void hmma_gemm_all_kernel() {
    extern __shared__ __align__(1024) char dsm[];
    uint32_t sbase = smem_u32(dsm);

    int tid = threadIdx.x;
    int wid = tid >> 5;
    int lane = tid & 31;

    // ---- tile decode: linear block id -> (m, browt, bcolt) ----
    int id = blockIdx.x;
    int m, local;
    if (id < 640)       { m = 0; local = id; }
    else if (id < 1664) { m = 1; local = id - 640; }
    else if (id < 2432) { m = 2; local = id - 1664; }
    else if (id < 2944) { m = 3; local = id - 2432; }
    else                { m = 4; local = id - 2944; }
    int K = c_K[m];
    int gx = K >> 7;                      // col tiles
    int bcolt = local % gx, browt = local / gx;
    int brow = browt << 7, bcol = bcolt << 7;

    const __half* A = g_U + (size_t)NS * c_P[m];
    const __half* B = g_W + c_Woff[m];
    float* C = g_Z + (size_t)NS * c_P[m];

    // ---- global->smem mapping: 2 threads/row, 4x16B each (64 fp16 = 128B) ----
    int r = tid >> 1, q = tid & 1;
    const char* gA = (const char*)(A + (size_t)(brow + r) * K + q * 32);
    const char* gB = (const char*)(B + (size_t)(bcol + r) * K + q * 32);
    uint32_t sts[4];
    #pragma unroll
    for (int i = 0; i < 4; i++) {
        uint32_t off = (uint32_t)r * 128u + (uint32_t)(q * 4 + i) * 16u;
        sts[i] = off ^ ((off >> 3) & 0x70);
    }

    // ---- per-warp compute layout ----
    int wm = wid >> 1, wn = wid & 1;
    uint32_t a_row[2], a_rx[2];
    #pragma unroll
    for (int mt = 0; mt < 2; mt++) {
        int row = wm * 32 + mt * 16 + (lane & 15);
        a_row[mt] = (uint32_t)row * 128u;
        a_rx[mt] = (uint32_t)(row & 7) << 4;
    }
    uint32_t a_cb = ((lane >> 4) & 1) * 16u;
    int nloc = (lane & 7) + ((lane & 16) >> 1);
    uint32_t b_row[4], b_rx[4];
    #pragma unroll
    for (int nt4 = 0; nt4 < 4; nt4++) {
        int nrow = wn * 64 + nt4 * 16 + nloc;
        b_row[nt4] = (uint32_t)nrow * 128u;
        b_rx[nt4] = (uint32_t)(nrow & 7) << 4;
    }
    uint32_t b_cb = ((lane >> 3) & 1) * 16u;

    float acc[2][8][4];
    #pragma unroll
    for (int mt = 0; mt < 2; mt++)
        #pragma unroll
        for (int nt = 0; nt < 8; nt++)
            #pragma unroll
            for (int e = 0; e < 4; e++) acc[mt][nt][e] = 0.f;

    int NC = K >> 6;

    // prologue: chunks 0,1 into stages 0,1
    #pragma unroll
    for (int p = 0; p < 2; p++) {
        uint32_t aS = sbase + (uint32_t)p * 32768u;
        uint32_t bS = aS + 16384u;
        const char* Ap = gA + (size_t)p * 128;
        const char* Bp = gB + (size_t)p * 128;
        #pragma unroll
        for (int i = 0; i < 4; i++) {
            CP_ASYNC16(aS + sts[i], Ap + i * 16);
            CP_ASYNC16(bS + sts[i], Bp + i * 16);
        }
        CP_COMMIT();
    }

    for (int c = 0; c < NC; ++c) {
        if (c + 1 < NC) CP_WAIT1(); else CP_WAIT0();
        __syncthreads();
        if (c + 2 < NC) {
            int s = c + 2; s -= (s >= 3) ? 3 : 0; s -= (s >= 3) ? 3 : 0;  // (c+2)%3 cheap
            int st = (c + 2) % 3;
            uint32_t aS = sbase + (uint32_t)st * 32768u;
            uint32_t bS = aS + 16384u;
            const char* Ap = gA + (size_t)(c + 2) * 128;
            const char* Bp = gB + (size_t)(c + 2) * 128;
            #pragma unroll
            for (int i = 0; i < 4; i++) {
                CP_ASYNC16(aS + sts[i], Ap + i * 16);
                CP_ASYNC16(bS + sts[i], Bp + i * 16);
            }
            CP_COMMIT();
        }
        int cst = c % 3;
        uint32_t aS = sbase + (uint32_t)cst * 32768u;
        uint32_t bS = aS + 16384u;
        #pragma unroll
        for (int kq = 0; kq < 4; kq++) {
            uint32_t kb = (uint32_t)kq * 32u;
            uint32_t afr[2][4];
            #pragma unroll
            for (int mt = 0; mt < 2; mt++)
                LDSM_X4(afr[mt][0], afr[mt][1], afr[mt][2], afr[mt][3],
                        aS + a_row[mt] + ((a_cb + kb) ^ a_rx[mt]));
            uint32_t bfr[4][4];
            #pragma unroll
            for (int nt4 = 0; nt4 < 4; nt4++)
                LDSM_X4(bfr[nt4][0], bfr[nt4][1], bfr[nt4][2], bfr[nt4][3],
                        bS + b_row[nt4] + ((b_cb + kb) ^ b_rx[nt4]));
            #pragma unroll
            for (int mt = 0; mt < 2; mt++)
                #pragma unroll
                for (int nt = 0; nt < 8; nt++)
                    hmma16816(acc[mt][nt], afr[mt], &bfr[nt >> 1][(nt & 1) * 2]);
        }
    }

    // epilogue
    int g2 = lane >> 2, t2 = lane & 3;
    #pragma unroll
    for (int mt = 0; mt < 2; mt++) {
        #pragma unroll
        for (int nt = 0; nt < 8; nt++) {
            int row0 = brow + wm * 32 + mt * 16 + g2;
            int col = bcol + wn * 64 + nt * 8 + t2 * 2;
            float2 v0 = make_float2(acc[mt][nt][0], acc[mt][nt][1]);
            float2 v1 = make_float2(acc[mt][nt][2], acc[mt][nt][3]);
            *(float2*)(C + (size_t)row0 * K + col) = v0;
            *(float2*)(C + (size_t)(row0 + 8) * K + col) = v1;
        }
    }
}

// =======================================================================
// Kernel 5: scatter Z back (+bias), rotate back, write out
// =======================================================================
__global__ void scatter_rot_kernel(const float* __restrict__ fc0_b, float* __restrict__ out) {
    int n = blockIdx.x;
    __shared__ float pre[DIMX];
    __shared__ float dt[164];
    for (int c = threadIdx.x; c < 164; c += 256) dt[c] = g_DT[(size_t)n * 164 + c];
    for (int e = threadIdx.x; e < DIMX; e += 256) {
        int m, j, l, k, i;
        decode_e(e, m, j, l, k, i);
        float v = g_Z[(size_t)NS * c_P[m] + (size_t)n * c_K[m] + j];
        if (m == 0) v += fc0_b[j];
        pre[128*l*l + k*(2*l + 1) + i] = v;
    }
    __syncthreads();
    for (int col = threadIdx.x; col < DIMX; col += 256) {
        int l;
        if (col < 128) l = 0;
        else if (col < 512) l = 1;
        else if (col < 1152) l = 2;
        else if (col < 2048) l = 3;
        else l = 4;
        float val;
        if (l == 0) {
            val = pre[col];
        } else {
            int off = 128*l*l;
            int d = 2*l + 1;
            int rr = col - off;
            int k = rr / d;
            int i = rr - k * d;
            const float* dd = dt + c_offD[l-1] + i*d;
            const float* pb = pre + off + k*d;
            float s = 0.f;
            for (int jj = 0; jj < d; jj++) s += dd[jj] * pb[jj];
            val = s;
        }
        out[(size_t)n * DIMX + col] = val;
    }
}

// =======================================================================
// launch
// =======================================================================
extern "C" void kernel_launch(void* const* d_in, const int* in_sizes, int n_in,
                              void* d_out, int out_size) {
    const float* x     = (const float*)d_in[0];
    const float* R     = (const float*)d_in[1];
    const float* fc0_w = (const float*)d_in[2];
    const float* fc0_b = (const float*)d_in[3];
    const float* w1    = (const float*)d_in[4];
    const float* w2    = (const float*)d_in[5];
    const float* w3    = (const float*)d_in[6];
    const float* w4    = (const float*)d_in[7];
    float* out = (float*)d_out;

    build_J_kernel<<<1, 384>>>();
    build_w_kernel<<<(2375680 + 255) / 256, 256>>>(fc0_w, w1, w2, w3, w4);
    wigner_kernel<<<(NS * 4 + 127) / 128, 128>>>(R);
    rot_gather_kernel<<<NS, 256>>>(x);

    cudaFuncSetAttribute(hmma_gemm_all_kernel,
                         cudaFuncAttributeMaxDynamicSharedMemorySize, 98304);
    hmma_gemm_all_kernel<<<3200, 256, 98304>>>();

    scatter_rot_kernel<<<NS, 256>>>(fc0_b, out);
}

// round 6
// speedup vs baseline: 6.0522x; 1.2331x over previous
#include <cuda_runtime.h>
#include <cuda_fp16.h>
#include <math.h>
#include <stdint.h>

// ---------------- problem constants ----------------
#define NS    16384
#define DIMX  3200
#define LMAX  4

__constant__ int c_offD[4] = {0, 9, 34, 83};

// 13 sub-GEMMs: 0: m0 (640x640); then per m=1..4: A, B, A+B (co x co)
// co = {512, 384, 256, 128}
__constant__ int cg_tileStart[14] = {0,640,1152,1664,2176,2560,2944,3328,3584,3840,4096,4224,4352,4480};
__constant__ int cg_Ksub[13]  = {640,512,512,512,384,384,384,256,256,256,128,128,128};
__constant__ int cg_UZp[13]   = {0,640,1152,1664,2176,2560,2944,3328,3584,3840,4096,4224,4352};
__constant__ int cg_Wpref[14] = {0,409600,671744,933888,1196032,1343488,1490944,1638400,1703936,1769472,1835008,1851392,1867776,1884160};

// ---------------- device scratch ----------------
__device__ float g_J[164];
__device__ float g_DT[(size_t)NS * 164];
__device__ __half g_W[1884160];                  // sub-GEMM weights fp16
__device__ __half g_U[(size_t)NS * 4480];        // sub-GEMM inputs fp16
__device__ float g_Z[(size_t)NS * 4480];         // sub-GEMM outputs fp32

// =======================================================================
// Kernel 0: build J matrices (reference algorithm, fp64, parallel)
// =======================================================================
__global__ void build_J_kernel() {
    __shared__ double Xr[4][81], Xi[4][81], Qr[4][81], Qi[4][81];
    __shared__ double Sa[4][81], Se[4][81], St[4][81];
    int g = threadIdx.x / 96;
    int e = threadIdx.x % 96;
    int l = g + 1, d = 2*l + 1, dd = d*d;
    const double j = (double)l;
    const double SQ12 = 0.70710678118654752440;
    const double PI_D = 3.14159265358979323846;

    if (e < 81) { Xr[g][e]=0; Xi[g][e]=0; Qr[g][e]=0; Qi[g][e]=0; }
    __syncthreads();
    if (e == 0) {
        for (int i2 = 0; i2 < d-1; i2++) {
            double m  = -j + (double)i2;
            double rv = -sqrt(j*(j+1.0) - m*(m+1.0));
            Xr[g][(i2+1)*d + i2] += 0.5 * rv;
            double m2 = -j + 1.0 + (double)i2;
            double lv = sqrt(j*(j+1.0) - m2*(m2-1.0));
            Xr[g][i2*d + (i2+1)] += 0.5 * lv;
        }
        for (int i2 = 0; i2 < d; i2++) Xi[g][i2*d + i2] += (-j + (double)i2);
        for (int m = 1; m <= l; m++) {
            int r = l - m;
            Qr[g][r*d + (l+m)] = SQ12;
            Qi[g][r*d + r]     = -SQ12;
            int r2 = l + m;
            double sgn = (m & 1) ? -1.0 : 1.0;
            Qr[g][r2*d + r2]     = sgn * SQ12;
            Qi[g][r2*d + (l-m)]  = sgn * SQ12;
        }
        Qr[g][l*d + l] = 1.0;
    }
    __syncthreads();
    if (e < dd) {
        int i = e / d, jj = e % d;
        double s = 0.0;
        for (int k = 0; k < d; k++) {
            double mr = 0.0, mi = 0.0;
            for (int p = 0; p < d; p++) {
                mr += Xr[g][k*d+p]*Qr[g][p*d+jj] - Xi[g][k*d+p]*Qi[g][p*d+jj];
                mi += Xr[g][k*d+p]*Qi[g][p*d+jj] + Xi[g][k*d+p]*Qr[g][p*d+jj];
            }
            s += Qr[g][k*d+i]*mr + Qi[g][k*d+i]*mi;
        }
        Sa[g][e] = (PI_D * SQ12) * s * (1.0/1024.0);
        Se[g][e] = (i == jj) ? 1.0 : 0.0;
        St[g][e] = (i == jj) ? 1.0 : 0.0;
    }
    __syncthreads();
    for (int k = 1; k < 24; k++) {
        double v = 0.0;
        if (e < dd) {
            int i = e / d, jj = e % d;
            double s = 0.0;
            for (int p = 0; p < d; p++) s += St[g][i*d+p] * Sa[g][p*d+jj];
            v = s / (double)k;
        }
        __syncthreads();
        if (e < dd) { St[g][e] = v; Se[g][e] += v; }
        __syncthreads();
    }
    for (int s2 = 0; s2 < 10; s2++) {
        double v = 0.0;
        if (e < dd) {
            int i = e / d, jj = e % d;
            double s = 0.0;
            for (int p = 0; p < d; p++) s += Se[g][i*d+p] * Se[g][p*d+jj];
            v = s;
        }
        __syncthreads();
        if (e < dd) Se[g][e] = v;
        __syncthreads();
    }
    if (e < dd) g_J[c_offD[g] + e] = (float)Se[g][e];
}

// =======================================================================
// Kernel 1: build W (fp16): sub 0 = fc0_w; subs 3m-2..3m: A, B, A+B
// =======================================================================
__global__ void build_w_kernel(const float* __restrict__ fc0_w,
                               const float* __restrict__ w1, const float* __restrict__ w2,
                               const float* __restrict__ w3, const float* __restrict__ w4) {
    int gid = blockIdx.x * blockDim.x + threadIdx.x;
    if (gid >= 1884160) return;
    int s = 0;
    #pragma unroll
    for (int q = 1; q < 13; q++) if (gid >= cg_Wpref[q]) s = q;
    int local = gid - cg_Wpref[s];
    int K = cg_Ksub[s];
    int o = local / K;
    int t = local - o * K;
    float v;
    if (s == 0) {
        v = fc0_w[o * 640 + t];
    } else {
        int m = (s - 1) / 3 + 1;
        int which = (s - 1) % 3;
        const float* w = (m == 1) ? w1 : (m == 2) ? w2 : (m == 3) ? w3 : w4;
        if (which == 0)      v = w[o * K + t];                      // A
        else if (which == 1) v = w[(K + o) * K + t];                // B
        else                 v = w[o * K + t] + w[(K + o) * K + t]; // A+B
    }
    g_W[gid] = __float2half_rn(v);
}

// =======================================================================
// Kernel 2: per-sample Wigner D^T (D = Z(a) J Z(b) J)
// =======================================================================
__global__ void wigner_kernel(const float* __restrict__ R) {
    int gid = blockIdx.x * blockDim.x + threadIdx.x;
    if (gid >= NS * 4) return;
    int n = gid >> 2;
    int l = (gid & 3) + 1;
    int d = 2*l + 1;

    float vx = R[n*3 + 1], vy = R[n*3 + 2], vz = R[n*3 + 0];
    float nrm = sqrtf(vx*vx + vy*vy + vz*vz);
    nrm = fmaxf(nrm, 1e-12f);
    vx /= nrm; vy /= nrm; vz /= nrm;
    vx = fminf(fmaxf(vx, -1.f), 1.f);
    vy = fminf(fmaxf(vy, -1.f), 1.f);
    vz = fminf(fmaxf(vz, -1.f), 1.f);
    float beta  = acosf(vy);
    float alpha = atan2f(vx, vz);

    const float* J = g_J + c_offD[l-1];
    float T1[81], T2[81], Dm[81];

    for (int i = 0; i < d; i++) {
        float fr = (float)(l - i);
        float c = cosf(fr * beta), s = sinf(fr * beta);
        int ri = d - 1 - i;
        for (int jj = 0; jj < d; jj++)
            T1[i*d + jj] = c * J[i*d + jj] + s * J[ri*d + jj];
    }
    for (int i = 0; i < d; i++)
        for (int jj = 0; jj < d; jj++) {
            float s = 0.f;
            for (int k = 0; k < d; k++) s += J[i*d + k] * T1[k*d + jj];
            T2[i*d + jj] = s;
        }
    for (int i = 0; i < d; i++) {
        float fr = (float)(l - i);
        float c = cosf(fr * alpha), s = sinf(fr * alpha);
        int ri = d - 1 - i;
        for (int jj = 0; jj < d; jj++)
            Dm[i*d + jj] = c * T2[i*d + jj] + s * T2[ri*d + jj];
    }
    float* dst = g_DT + (size_t)n * 164 + c_offD[l-1];
    for (int i = 0; i < d; i++)
        for (int jj = 0; jj < d; jj++)
            dst[i*d + jj] = Dm[jj*d + i];
}

// =======================================================================
// Kernel 3: rotate x (specialized per l), gather into fp16 sub-GEMM inputs
// =======================================================================
__global__ __launch_bounds__(256) void rot_gather_kernel(const float* __restrict__ x) {
    int n = blockIdx.x;
    __shared__ float xs[DIMX];
    __shared__ float xrot[DIMX];
    __shared__ float dt[164];
    const float* xr = x + (size_t)n * DIMX;
    for (int c = threadIdx.x; c < DIMX; c += 256) xs[c] = xr[c];
    for (int c = threadIdx.x; c < 164; c += 256) dt[c] = g_DT[(size_t)n * 164 + c];
    __syncthreads();

    // phase 1: xrot = blockdiag(D^T rows) applied per (l,k)
    #define ROTF(CNT, D, DTO, XO)                                        \
    for (int idx = threadIdx.x; idx < CNT; idx += 256) {                 \
        int k = idx / D, i = idx - k * D;                                \
        const float* dd = dt + DTO + i * D;                              \
        const float* xb = xs + XO + k * D;                               \
        float v = 0.f;                                                   \
        _Pragma("unroll")                                                \
        for (int jj = 0; jj < D; jj++) v += dd[jj] * xb[jj];             \
        xrot[XO + idx] = v;                                              \
    }
    ROTF(384, 3, 0, 128)
    ROTF(640, 5, 9, 512)
    ROTF(896, 7, 34, 1152)
    ROTF(1152, 9, 83, 2048)
    __syncthreads();

    // phase 2: gather into U
    for (int j = threadIdx.x; j < 640; j += 256) {
        int l = j >> 7, k = j & 127;
        float v = (l == 0) ? 0.f : xrot[128*l*l + k*(2*l + 1) + l];
        g_U[(size_t)n * 640 + j] = __float2half_rn(v);
    }
    #define GATH(MM, CO, P0, P1, P2)                                         \
    for (int t = threadIdx.x; t < CO; t += 256) {                            \
        int c0 = t & 1, ph = t >> 1;                                         \
        int p1 = (CO >> 1) + ph;                                             \
        int l0 = MM + (ph >> 7), k0 = ph & 127;                              \
        int l1 = MM + (p1 >> 7), k1 = p1 & 127;                              \
        int i0 = c0 ? (l0 + MM) : (l0 - MM);                                 \
        int i1 = c0 ? (l1 + MM) : (l1 - MM);                                 \
        float u0 = xrot[128*l0*l0 + k0*(2*l0 + 1) + i0];                     \
        float u1 = xrot[128*l1*l1 + k1*(2*l1 + 1) + i1];                     \
        g_U[(size_t)NS * P0 + (size_t)n * CO + t] = __float2half_rn(u0);     \
        g_U[(size_t)NS * P1 + (size_t)n * CO + t] = __float2half_rn(u1);     \
        g_U[(size_t)NS * P2 + (size_t)n * CO + t] = __float2half_rn(u0 + u1);\
    }
    GATH(1, 512, 640, 1152, 1664)
    GATH(2, 384, 2176, 2560, 2944)
    GATH(3, 256, 3328, 3584, 3840)
    GATH(4, 128, 4096, 4224, 4352)
}

// =======================================================================
// Kernel 4: HMMA fp16 GEMM over 13 sub-GEMMs (square co x co, K chunks 64)
// =======================================================================
__device__ __forceinline__ uint32_t smem_u32(const void* p) {
    uint32_t a;
    asm("{ .reg .u64 t; cvta.to.shared.u64 t, %1; cvt.u32.u64 %0, t; }" : "=r"(a) : "l"(p));
    return a;
}
#define CP_ASYNC16(dst, src) \
    asm volatile("cp.async.cg.shared.global [%0], [%1], 16;" :: "r"(dst), "l"(src) : "memory")
#define CP_COMMIT() asm volatile("cp.async.commit_group;" ::: "memory")
#define CP_WAIT1()  asm volatile("cp.async.wait_group 1;" ::: "memory")
#define CP_WAIT0()  asm volatile("cp.async.wait_group 0;" ::: "memory")
#define LDSM_X4(r0, r1, r2, r3, addr) \
    asm volatile("ldmatrix.sync.aligned.m8n8.x4.shared.b16 {%0,%1,%2,%3}, [%4];" \
                 : "=r"(r0), "=r"(r1), "=r"(r2), "=r"(r3) : "r"(addr))

__device__ __forceinline__ void hmma16816(float* c, const uint32_t* a, const uint32_t* b) {
    asm volatile(
        "mma.sync.aligned.m16n8k16.row.col.f32.f16.f16.f32 "
        "{%0,%1,%2,%3}, {%4,%5,%6,%7}, {%8,%9}, {%0,%1,%2,%3};"
        : "+f"(c[0]), "+f"(c[1]), "+f"(c[2]), "+f"(c[3])
        : "r"(a[0]), "r"(a[1]), "r"(a[2]), "r"(a[3]), "r"(b[0]), "r"(b[1]));
}

__global__ __launch_bounds__(256) void hmma_gemm_all_kernel() {
    extern __shared__ __align__(1024) char dsm[];
    uint32_t sbase = smem_u32(dsm);

    int tid = threadIdx.x;
    int wid = tid >> 5;
    int lane = tid & 31;

    // ---- tile decode ----
    int id = blockIdx.x;
    int s = 0;
    #pragma unroll
    for (int q = 1; q < 13; q++) if (id >= cg_tileStart[q]) s = q;
    int local = id - cg_tileStart[s];
    int K = cg_Ksub[s];
    int gx = K >> 7;
    int bcolt = local % gx, browt = local / gx;
    int brow = browt << 7, bcol = bcolt << 7;

    const __half* A = g_U + (size_t)NS * cg_UZp[s];
    const __half* B = g_W + cg_Wpref[s];
    float* C = g_Z + (size_t)NS * cg_UZp[s];

    // ---- global->smem: 2 threads/row, 4x16B each (64 fp16 = 128B) ----
    int r = tid >> 1, q2 = tid & 1;
    const char* gA = (const char*)(A + (size_t)(brow + r) * K + q2 * 32);
    const char* gB = (const char*)(B + (size_t)(bcol + r) * K + q2 * 32);
    uint32_t sts[4];
    #pragma unroll
    for (int i = 0; i < 4; i++) {
        uint32_t off = (uint32_t)r * 128u + (uint32_t)(q2 * 4 + i) * 16u;
        sts[i] = off ^ ((off >> 3) & 0x70);
    }

    // ---- per-warp compute layout ----
    int wm = wid >> 1, wn = wid & 1;
    uint32_t a_row[2], a_rx[2];
    #pragma unroll
    for (int mt = 0; mt < 2; mt++) {
        int row = wm * 32 + mt * 16 + (lane & 15);
        a_row[mt] = (uint32_t)row * 128u;
        a_rx[mt] = (uint32_t)(row & 7) << 4;
    }
    uint32_t a_cb = ((lane >> 4) & 1) * 16u;
    int nloc = (lane & 7) + ((lane & 16) >> 1);
    uint32_t b_row[4], b_rx[4];
    #pragma unroll
    for (int nt4 = 0; nt4 < 4; nt4++) {
        int nrow = wn * 64 + nt4 * 16 + nloc;
        b_row[nt4] = (uint32_t)nrow * 128u;
        b_rx[nt4] = (uint32_t)(nrow & 7) << 4;
    }
    uint32_t b_cb = ((lane >> 3) & 1) * 16u;

    float acc[2][8][4];
    #pragma unroll
    for (int mt = 0; mt < 2; mt++)
        #pragma unroll
        for (int nt = 0; nt < 8; nt++)
            #pragma unroll
            for (int e = 0; e < 4; e++) acc[mt][nt][e] = 0.f;

    int NC = K >> 6;

    // prologue: chunks 0,1 into stages 0,1 (NC >= 2 always)
    #pragma unroll
    for (int p = 0; p < 2; p++) {
        uint32_t aS = sbase + (uint32_t)p * 32768u;
        uint32_t bS = aS + 16384u;
        const char* Ap = gA + (size_t)p * 128;
        const char* Bp = gB + (size_t)p * 128;
        #pragma unroll
        for (int i = 0; i < 4; i++) {
            CP_ASYNC16(aS + sts[i], Ap + i * 16);
            CP_ASYNC16(bS + sts[i], Bp + i * 16);
        }
        CP_COMMIT();
    }

    for (int c = 0; c < NC; ++c) {
        if (c + 1 < NC) CP_WAIT1(); else CP_WAIT0();
        __syncthreads();
        if (c + 2 < NC) {
            int st = (c + 2) % 3;
            uint32_t aS = sbase + (uint32_t)st * 32768u;
            uint32_t bS = aS + 16384u;
            const char* Ap = gA + (size_t)(c + 2) * 128;
            const char* Bp = gB + (size_t)(c + 2) * 128;
            #pragma unroll
            for (int i = 0; i < 4; i++) {
                CP_ASYNC16(aS + sts[i], Ap + i * 16);
                CP_ASYNC16(bS + sts[i], Bp + i * 16);
            }
            CP_COMMIT();
        }
        int cst = c % 3;
        uint32_t aS = sbase + (uint32_t)cst * 32768u;
        uint32_t bS = aS + 16384u;
        #pragma unroll
        for (int kq = 0; kq < 4; kq++) {
            uint32_t kb = (uint32_t)kq * 32u;
            uint32_t afr[2][4];
            #pragma unroll
            for (int mt = 0; mt < 2; mt++)
                LDSM_X4(afr[mt][0], afr[mt][1], afr[mt][2], afr[mt][3],
                        aS + a_row[mt] + ((a_cb + kb) ^ a_rx[mt]));
            uint32_t bfr[4][4];
            #pragma unroll
            for (int nt4 = 0; nt4 < 4; nt4++)
                LDSM_X4(bfr[nt4][0], bfr[nt4][1], bfr[nt4][2], bfr[nt4][3],
                        bS + b_row[nt4] + ((b_cb + kb) ^ b_rx[nt4]));
            #pragma unroll
            for (int mt = 0; mt < 2; mt++)
                #pragma unroll
                for (int nt = 0; nt < 8; nt++)
                    hmma16816(acc[mt][nt], afr[mt], &bfr[nt >> 1][(nt & 1) * 2]);
        }
    }

    // epilogue
    int g2 = lane >> 2, t2 = lane & 3;
    #pragma unroll
    for (int mt = 0; mt < 2; mt++) {
        #pragma unroll
        for (int nt = 0; nt < 8; nt++) {
            int row0 = brow + wm * 32 + mt * 16 + g2;
            int col = bcol + wn * 64 + nt * 8 + t2 * 2;
            float2 v0 = make_float2(acc[mt][nt][0], acc[mt][nt][1]);
            float2 v1 = make_float2(acc[mt][nt][2], acc[mt][nt][3]);
            *(float2*)(C + (size_t)row0 * K + col) = v0;
            *(float2*)(C + (size_t)(row0 + 8) * K + col) = v1;
        }
    }
}

// =======================================================================
// Kernel 5: combine Karatsuba outputs (+bias), rotate back, write out
// =======================================================================
__global__ __launch_bounds__(256) void scatter_rot_kernel(const float* __restrict__ fc0_b,
                                                          float* __restrict__ out) {
    int n = blockIdx.x;
    __shared__ float pre[DIMX];
    __shared__ float dt[164];
    for (int c = threadIdx.x; c < 164; c += 256) dt[c] = g_DT[(size_t)n * 164 + c];

    for (int j = threadIdx.x; j < 640; j += 256) {
        int l = j >> 7, k = j & 127;
        pre[128*l*l + k*(2*l + 1) + l] = g_Z[(size_t)n * 640 + j] + fc0_b[j];
    }
    #define SCAT(MM, CO, P0, P1, P2)                                         \
    for (int t = threadIdx.x; t < CO; t += 256) {                            \
        float v1 = g_Z[(size_t)NS * P0 + (size_t)n * CO + t];                \
        float v2 = g_Z[(size_t)NS * P1 + (size_t)n * CO + t];                \
        float v3 = g_Z[(size_t)NS * P2 + (size_t)n * CO + t];                \
        float re = v1 - v2, im = v3 - v1 - v2;                               \
        int c0 = t & 1, ph = t >> 1;                                         \
        int p1 = (CO >> 1) + ph;                                             \
        int l0 = MM + (ph >> 7), k0 = ph & 127;                              \
        int l1 = MM + (p1 >> 7), k1 = p1 & 127;                              \
        int i0 = c0 ? (l0 + MM) : (l0 - MM);                                 \
        int i1 = c0 ? (l1 + MM) : (l1 - MM);                                 \
        pre[128*l0*l0 + k0*(2*l0 + 1) + i0] = re;                            \
        pre[128*l1*l1 + k1*(2*l1 + 1) + i1] = im;                            \
    }
    SCAT(1, 512, 640, 1152, 1664)
    SCAT(2, 384, 2176, 2560, 2944)
    SCAT(3, 256, 3328, 3584, 3840)
    SCAT(4, 128, 4096, 4224, 4352)
    __syncthreads();

    float* orow = out + (size_t)n * DIMX;
    for (int c = threadIdx.x; c < 128; c += 256) orow[c] = pre[c];
    #define ROTB(CNT, D, DTO, XO)                                        \
    for (int idx = threadIdx.x; idx < CNT; idx += 256) {                 \
        int k = idx / D, i = idx - k * D;                                \
        const float* dd = dt + DTO + i * D;                              \
        const float* pb = pre + XO + k * D;                              \
        float v = 0.f;                                                   \
        _Pragma("unroll")                                                \
        for (int jj = 0; jj < D; jj++) v += dd[jj] * pb[jj];             \
        orow[XO + idx] = v;                                              \
    }
    ROTB(384, 3, 0, 128)
    ROTB(640, 5, 9, 512)
    ROTB(896, 7, 34, 1152)
    ROTB(1152, 9, 83, 2048)
}

// =======================================================================
// launch
// =======================================================================
extern "C" void kernel_launch(void* const* d_in, const int* in_sizes, int n_in,
                              void* d_out, int out_size) {
    const float* x     = (const float*)d_in[0];
    const float* R     = (const float*)d_in[1];
    const float* fc0_w = (const float*)d_in[2];
    const float* fc0_b = (const float*)d_in[3];
    const float* w1    = (const float*)d_in[4];
    const float* w2    = (const float*)d_in[5];
    const float* w3    = (const float*)d_in[6];
    const float* w4    = (const float*)d_in[7];
    float* out = (float*)d_out;

    build_J_kernel<<<1, 384>>>();
    build_w_kernel<<<(1884160 + 255) / 256, 256>>>(fc0_w, w1, w2, w3, w4);
    wigner_kernel<<<(NS * 4 + 127) / 128, 128>>>(R);
    rot_gather_kernel<<<NS, 256>>>(x);

    cudaFuncSetAttribute(hmma_gemm_all_kernel,
                         cudaFuncAttributeMaxDynamicSharedMemorySize, 98304);
    hmma_gemm_all_kernel<<<4480, 256, 98304>>>();

    scatter_rot_kernel<<<NS, 256>>>(fc0_b, out);
}